// round 14
// baseline (speedup 1.0000x reference)
#include <cuda_runtime.h>

// Locally-connected 3x3 conv, unshared weights:
// out[b,i,j] = 9 * sum_{m,n} x[b,i+m,j+n] * w[i,j,3m+n] + sum_k b[i,j,k]
// x zero-padded on the high side of both spatial dims.
//
// 2x2 output patch per thread: rows (i,i+1) x cols (j,j+1) need input rows
// i..i+3 x cols j..j+3 = 8 LDG.64 for 4 outputs (vs 12 in the 1x2 scheme).
// Block = 128 threads = jt(16 col-pairs) x ip(2 row-pairs) x bq(4).
// Block covers 4 rows x 32 cols x 64 batches -> weight tile staged once.
// Grid (8,64) = 512 blocks; launch_bounds(128,6) -> 85-reg cap ->
// capacity 888 >= 512: all blocks co-resident, single wave, no tail.

#define Wd 256
#define Hd 256
#define IMG 65536u            // Wd*Hd, fits in 32-bit offsets

__global__ __launch_bounds__(128, 6)
void lc_kernel(const float* __restrict__ x,
               const float* __restrict__ w,
               const float* __restrict__ bvec,
               float* __restrict__ out) {
    __shared__ float ws[1152];   // [row*288 + col*9 + k], 4 rows x 32 cols x 9
    __shared__ float bs[1152];

    const int t  = threadIdx.x;
    const int jt = t & 15;          // 0..15 : column pair
    const int ip = (t >> 4) & 1;    // 0..1  : row pair
    const int bq = t >> 5;          // 0..3  : 16-batch group

    const int i0 = blockIdx.y * 4;
    const int j0 = blockIdx.x * 32;
    const int i  = i0 + ip * 2;     // first output row of this thread
    const int j  = j0 + jt * 2;     // first output col

    // ---- stage w/b tile (coalesced), once per block; tiles disjoint ----
    #pragma unroll
    for (int idx = t; idx < 1152; idx += 128) {
        int r    = idx / 288;
        int rest = idx - r * 288;        // 32 cols * 9 units
        unsigned g = ((unsigned)(i0 + r) * Hd + j0) * 9u + rest;
        ws[idx] = w[g];
        bs[idx] = bvec[g];
    }
    __syncthreads();

    // ---- per-thread weights (2 rows x 2 cols x 9) + bias sums ----
    float wr[2][2][9];
    float bsum[2][2];
    #pragma unroll
    for (int r = 0; r < 2; r++) {
        #pragma unroll
        for (int c = 0; c < 2; c++) {
            const int base = (ip * 2 + r) * 288 + (jt * 2 + c) * 9;
            float s = 0.f;
            #pragma unroll
            for (int k = 0; k < 9; k++) {
                wr[r][c][k] = ws[base + k];
                s += bs[base + k];
            }
            bsum[r][c] = s;
        }
    }

    // predicates: cols j,j+1 always valid; cols j+2,j+3 valid iff j+2<Hd.
    // input row i+1 always valid (i <= 254); rows i+2,i+3 predicated.
    const bool qok  = (j + 2 < Hd);
    const bool r2ok = (i + 2 < Wd);
    const bool r3ok = (i + 3 < Wd);
    const float2 z2 = make_float2(0.f, 0.f);

    unsigned off = (unsigned)(bq * 16) * IMG + (unsigned)i * Hd + (unsigned)j;

    #pragma unroll 2
    for (int bi = 0; bi < 16; bi++) {
        const float* xb = x + off;

        float2 a0 = *(const float2*)xb;
        float2 q0 = qok ? *(const float2*)(xb + 2) : z2;
        float2 a1 = *(const float2*)(xb + Hd);
        float2 q1 = qok ? *(const float2*)(xb + Hd + 2) : z2;
        float2 a2, q2, a3, q3;
        if (r2ok) {
            a2 = *(const float2*)(xb + 2 * Hd);
            q2 = qok ? *(const float2*)(xb + 2 * Hd + 2) : z2;
        } else { a2 = z2; q2 = z2; }
        if (r3ok) {
            a3 = *(const float2*)(xb + 3 * Hd);
            q3 = qok ? *(const float2*)(xb + 3 * Hd + 2) : z2;
        } else { a3 = z2; q3 = z2; }

        // v[row][col 0..3]
        const float v0[4] = {a0.x, a0.y, q0.x, q0.y};
        const float v1[4] = {a1.x, a1.y, q1.x, q1.y};
        const float v2[4] = {a2.x, a2.y, q2.x, q2.y};
        const float v3[4] = {a3.x, a3.y, q3.x, q3.y};

        float o00 = 0.f, o01 = 0.f, o10 = 0.f, o11 = 0.f;
        #pragma unroll
        for (int n = 0; n < 3; n++) {
            o00 = fmaf(v0[n],     wr[0][0][n],     o00);
            o00 = fmaf(v1[n],     wr[0][0][3 + n], o00);
            o00 = fmaf(v2[n],     wr[0][0][6 + n], o00);
            o01 = fmaf(v0[n + 1], wr[0][1][n],     o01);
            o01 = fmaf(v1[n + 1], wr[0][1][3 + n], o01);
            o01 = fmaf(v2[n + 1], wr[0][1][6 + n], o01);
            o10 = fmaf(v1[n],     wr[1][0][n],     o10);
            o10 = fmaf(v2[n],     wr[1][0][3 + n], o10);
            o10 = fmaf(v3[n],     wr[1][0][6 + n], o10);
            o11 = fmaf(v1[n + 1], wr[1][1][n],     o11);
            o11 = fmaf(v2[n + 1], wr[1][1][3 + n], o11);
            o11 = fmaf(v3[n + 1], wr[1][1][6 + n], o11);
        }

        *(float2*)(out + off)      = make_float2(fmaf(9.f, o00, bsum[0][0]),
                                                 fmaf(9.f, o01, bsum[0][1]));
        *(float2*)(out + off + Hd) = make_float2(fmaf(9.f, o10, bsum[1][0]),
                                                 fmaf(9.f, o11, bsum[1][1]));
        off += IMG;
    }
}

extern "C" void kernel_launch(void* const* d_in, const int* in_sizes, int n_in,
                              void* d_out, int out_size) {
    const float* x   = (const float*)d_in[0];
    const float* w   = (const float*)d_in[1];
    const float* b   = (const float*)d_in[2];
    float*       out = (float*)d_out;

    dim3 grid(8, 64);   // (col-tiles of 32, row-tiles of 4)
    lc_kernel<<<grid, 128>>>(x, w, b, out);
}

// round 15
// speedup vs baseline: 1.0068x; 1.0068x over previous
#include <cuda_runtime.h>

// Locally-connected 3x3 conv, unshared weights:
// out[b,i,j] = 9 * sum_{m,n} x[b,i+m,j+n] * w[i,j,3m+n] + sum_k b[i,j,k]
// x zero-padded on the high side of both spatial dims.
//
// 2x2 output patch per thread (8 LDG.64 per 4 outputs) combined with
// 256-thread blocks for occupancy.
// Block = 256 threads = jt(16 col-pairs) x ip(2 row-pairs) x bq(8).
// Each thread: 2x2 patch x 8 consecutive batches (b = bq*8 + bi).
// Block covers 4 rows x 32 cols x 64 batches -> weight tile staged once.
// Grid (8,64) = 512 blocks; launch_bounds(256,4) -> 64-reg cap ->
// capacity 592 >= 512: single wave, no tail; ~43% occupancy.

#define Wd 256
#define Hd 256
#define IMG 65536u            // Wd*Hd, fits in 32-bit offsets

__global__ __launch_bounds__(256, 4)
void lc_kernel(const float* __restrict__ x,
               const float* __restrict__ w,
               const float* __restrict__ bvec,
               float* __restrict__ out) {
    __shared__ float ws[1152];   // [row*288 + col*9 + k], 4 rows x 32 cols x 9
    __shared__ float bs[1152];

    const int t  = threadIdx.x;
    const int jt = t & 15;          // 0..15 : column pair
    const int ip = (t >> 4) & 1;    // 0..1  : row pair
    const int bq = t >> 5;          // 0..7  : 8-batch group

    const int i0 = blockIdx.y * 4;
    const int j0 = blockIdx.x * 32;
    const int i  = i0 + ip * 2;     // first output row of this thread
    const int j  = j0 + jt * 2;     // first output col

    // ---- stage w/b tile (coalesced), once per block; tiles disjoint ----
    #pragma unroll
    for (int idx = t; idx < 1152; idx += 256) {
        int r    = idx / 288;
        int rest = idx - r * 288;        // 32 cols * 9 units
        unsigned g = ((unsigned)(i0 + r) * Hd + j0) * 9u + rest;
        ws[idx] = w[g];
        bs[idx] = bvec[g];
    }
    __syncthreads();

    // ---- per-thread weights (2 rows x 2 cols x 9) + bias sums ----
    float wr[2][2][9];
    float bsum[2][2];
    #pragma unroll
    for (int r = 0; r < 2; r++) {
        #pragma unroll
        for (int c = 0; c < 2; c++) {
            const int base = (ip * 2 + r) * 288 + (jt * 2 + c) * 9;
            float s = 0.f;
            #pragma unroll
            for (int k = 0; k < 9; k++) {
                wr[r][c][k] = ws[base + k];
                s += bs[base + k];
            }
            bsum[r][c] = s;
        }
    }

    // predicates: cols j,j+1 always valid; cols j+2,j+3 valid iff j+2<Hd.
    // input row i+1 always valid (i <= 254); rows i+2,i+3 predicated.
    const bool qok  = (j + 2 < Hd);
    const bool r2ok = (i + 2 < Wd);
    const bool r3ok = (i + 3 < Wd);
    const float2 z2 = make_float2(0.f, 0.f);

    unsigned off = (unsigned)(bq * 8) * IMG + (unsigned)i * Hd + (unsigned)j;

    #pragma unroll 2
    for (int bi = 0; bi < 8; bi++) {
        const float* xb = x + off;

        float2 a0 = *(const float2*)xb;
        float2 q0 = qok ? *(const float2*)(xb + 2) : z2;
        float2 a1 = *(const float2*)(xb + Hd);
        float2 q1 = qok ? *(const float2*)(xb + Hd + 2) : z2;
        float2 a2, q2, a3, q3;
        if (r2ok) {
            a2 = *(const float2*)(xb + 2 * Hd);
            q2 = qok ? *(const float2*)(xb + 2 * Hd + 2) : z2;
        } else { a2 = z2; q2 = z2; }
        if (r3ok) {
            a3 = *(const float2*)(xb + 3 * Hd);
            q3 = qok ? *(const float2*)(xb + 3 * Hd + 2) : z2;
        } else { a3 = z2; q3 = z2; }

        // v[row][col 0..3]
        const float v0[4] = {a0.x, a0.y, q0.x, q0.y};
        const float v1[4] = {a1.x, a1.y, q1.x, q1.y};
        const float v2[4] = {a2.x, a2.y, q2.x, q2.y};
        const float v3[4] = {a3.x, a3.y, q3.x, q3.y};

        float o00 = 0.f, o01 = 0.f, o10 = 0.f, o11 = 0.f;
        #pragma unroll
        for (int n = 0; n < 3; n++) {
            o00 = fmaf(v0[n],     wr[0][0][n],     o00);
            o00 = fmaf(v1[n],     wr[0][0][3 + n], o00);
            o00 = fmaf(v2[n],     wr[0][0][6 + n], o00);
            o01 = fmaf(v0[n + 1], wr[0][1][n],     o01);
            o01 = fmaf(v1[n + 1], wr[0][1][3 + n], o01);
            o01 = fmaf(v2[n + 1], wr[0][1][6 + n], o01);
            o10 = fmaf(v1[n],     wr[1][0][n],     o10);
            o10 = fmaf(v2[n],     wr[1][0][3 + n], o10);
            o10 = fmaf(v3[n],     wr[1][0][6 + n], o10);
            o11 = fmaf(v1[n + 1], wr[1][1][n],     o11);
            o11 = fmaf(v2[n + 1], wr[1][1][3 + n], o11);
            o11 = fmaf(v3[n + 1], wr[1][1][6 + n], o11);
        }

        *(float2*)(out + off)      = make_float2(fmaf(9.f, o00, bsum[0][0]),
                                                 fmaf(9.f, o01, bsum[0][1]));
        *(float2*)(out + off + Hd) = make_float2(fmaf(9.f, o10, bsum[1][0]),
                                                 fmaf(9.f, o11, bsum[1][1]));
        off += IMG;
    }
}

extern "C" void kernel_launch(void* const* d_in, const int* in_sizes, int n_in,
                              void* d_out, int out_size) {
    const float* x   = (const float*)d_in[0];
    const float* w   = (const float*)d_in[1];
    const float* b   = (const float*)d_in[2];
    float*       out = (float*)d_out;

    dim3 grid(8, 64);   // (col-tiles of 32, row-tiles of 4)
    lc_kernel<<<grid, 256>>>(x, w, b, out);
}

// round 16
// speedup vs baseline: 1.1532x; 1.1455x over previous
#include <cuda_runtime.h>

// Locally-connected 3x3 conv, unshared weights:
// out[b,i,j] = 9 * sum_{m,n} x[b,i+m,j+n] * w[i,j,3m+n] + sum_k b[i,j,k]
// x zero-padded on the high side of both spatial dims.
//
// 2x2 output patch per thread (8 LDG.64 per 4 outputs), 256-thread blocks.
// Block = 256 threads = jt(16 col-pairs) x ip(2 row-pairs) x bq(8).
// Each thread: 2x2 patch x 8 consecutive batches (b = bq*8 + bi).
// Block covers 4 rows x 32 cols x 64 batches -> weight tile staged once.
// Grid (8,64) = 512 blocks; launch_bounds(256,4) -> 64-reg cap ->
// capacity 592 >= 512: single wave, no tail.
// unroll 1 keeps live regs ~60 <= 64: NO SPILL (R15's unroll 2 spilled;
// its live set was ~72 and L1% jumped 23->37).

#define Wd 256
#define Hd 256
#define IMG 65536u            // Wd*Hd, fits in 32-bit offsets

__global__ __launch_bounds__(256, 4)
void lc_kernel(const float* __restrict__ x,
               const float* __restrict__ w,
               const float* __restrict__ bvec,
               float* __restrict__ out) {
    __shared__ float ws[1152];   // [row*288 + col*9 + k], 4 rows x 32 cols x 9
    __shared__ float bs[1152];

    const int t  = threadIdx.x;
    const int jt = t & 15;          // 0..15 : column pair
    const int ip = (t >> 4) & 1;    // 0..1  : row pair
    const int bq = t >> 5;          // 0..7  : 8-batch group

    const int i0 = blockIdx.y * 4;
    const int j0 = blockIdx.x * 32;
    const int i  = i0 + ip * 2;     // first output row of this thread
    const int j  = j0 + jt * 2;     // first output col

    // ---- stage w/b tile (coalesced), once per block; tiles disjoint ----
    #pragma unroll
    for (int idx = t; idx < 1152; idx += 256) {
        int r    = idx / 288;
        int rest = idx - r * 288;        // 32 cols * 9 units
        unsigned g = ((unsigned)(i0 + r) * Hd + j0) * 9u + rest;
        ws[idx] = w[g];
        bs[idx] = bvec[g];
    }
    __syncthreads();

    // ---- per-thread weights (2 rows x 2 cols x 9) + bias sums ----
    float wr[2][2][9];
    float bsum[2][2];
    #pragma unroll
    for (int r = 0; r < 2; r++) {
        #pragma unroll
        for (int c = 0; c < 2; c++) {
            const int base = (ip * 2 + r) * 288 + (jt * 2 + c) * 9;
            float s = 0.f;
            #pragma unroll
            for (int k = 0; k < 9; k++) {
                wr[r][c][k] = ws[base + k];
                s += bs[base + k];
            }
            bsum[r][c] = s;
        }
    }

    // predicates: cols j,j+1 always valid; cols j+2,j+3 valid iff j+2<Hd.
    // input row i+1 always valid (i <= 254); rows i+2,i+3 predicated.
    const bool qok  = (j + 2 < Hd);
    const bool r2ok = (i + 2 < Wd);
    const bool r3ok = (i + 3 < Wd);
    const float2 z2 = make_float2(0.f, 0.f);

    unsigned off = (unsigned)(bq * 8) * IMG + (unsigned)i * Hd + (unsigned)j;

    #pragma unroll 1
    for (int bi = 0; bi < 8; bi++) {
        const float* xb = x + off;

        // all 8 loads issue up front: within-iteration MLP = 8
        float2 a0 = *(const float2*)xb;
        float2 q0 = qok ? *(const float2*)(xb + 2) : z2;
        float2 a1 = *(const float2*)(xb + Hd);
        float2 q1 = qok ? *(const float2*)(xb + Hd + 2) : z2;
        float2 a2, q2, a3, q3;
        if (r2ok) {
            a2 = *(const float2*)(xb + 2 * Hd);
            q2 = qok ? *(const float2*)(xb + 2 * Hd + 2) : z2;
        } else { a2 = z2; q2 = z2; }
        if (r3ok) {
            a3 = *(const float2*)(xb + 3 * Hd);
            q3 = qok ? *(const float2*)(xb + 3 * Hd + 2) : z2;
        } else { a3 = z2; q3 = z2; }

        // v[row][col 0..3]
        const float v0[4] = {a0.x, a0.y, q0.x, q0.y};
        const float v1[4] = {a1.x, a1.y, q1.x, q1.y};
        const float v2[4] = {a2.x, a2.y, q2.x, q2.y};
        const float v3[4] = {a3.x, a3.y, q3.x, q3.y};

        float o00 = 0.f, o01 = 0.f, o10 = 0.f, o11 = 0.f;
        #pragma unroll
        for (int n = 0; n < 3; n++) {
            o00 = fmaf(v0[n],     wr[0][0][n],     o00);
            o00 = fmaf(v1[n],     wr[0][0][3 + n], o00);
            o00 = fmaf(v2[n],     wr[0][0][6 + n], o00);
            o01 = fmaf(v0[n + 1], wr[0][1][n],     o01);
            o01 = fmaf(v1[n + 1], wr[0][1][3 + n], o01);
            o01 = fmaf(v2[n + 1], wr[0][1][6 + n], o01);
            o10 = fmaf(v1[n],     wr[1][0][n],     o10);
            o10 = fmaf(v2[n],     wr[1][0][3 + n], o10);
            o10 = fmaf(v3[n],     wr[1][0][6 + n], o10);
            o11 = fmaf(v1[n + 1], wr[1][1][n],     o11);
            o11 = fmaf(v2[n + 1], wr[1][1][3 + n], o11);
            o11 = fmaf(v3[n + 1], wr[1][1][6 + n], o11);
        }

        *(float2*)(out + off)      = make_float2(fmaf(9.f, o00, bsum[0][0]),
                                                 fmaf(9.f, o01, bsum[0][1]));
        *(float2*)(out + off + Hd) = make_float2(fmaf(9.f, o10, bsum[1][0]),
                                                 fmaf(9.f, o11, bsum[1][1]));
        off += IMG;
    }
}

extern "C" void kernel_launch(void* const* d_in, const int* in_sizes, int n_in,
                              void* d_out, int out_size) {
    const float* x   = (const float*)d_in[0];
    const float* w   = (const float*)d_in[1];
    const float* b   = (const float*)d_in[2];
    float*       out = (float*)d_out;

    dim3 grid(8, 64);   // (col-tiles of 32, row-tiles of 4)
    lc_kernel<<<grid, 256>>>(x, w, b, out);
}